// round 14
// baseline (speedup 1.0000x reference)
#include <cuda_runtime.h>
#include <cstdint>

#define GD 256
#define GH 256
#define GW 256
#define NT 16
#define TS 16
#define RWIN 6
#define DHW_I 16777216
#define NTILES 4096
#define NBUCK (NTILES * 8)      // per (tile, z-slice) buckets
#define CAP2 128                // pairs per slice bucket (lambda ~16)
#define MAXN 32768

// zero-initialized at module load; splat resets cursors each replay
__device__ int    g_cursors2[NBUCK];
__device__ uint2  g_pairs2 [NBUCK * CAP2];   // 32 MB static scratch
__device__ float4 g_params [MAXN * 3];  // {cx,cy,cz,C00},{C11,C22,S01,S02},{S12,wr,wi,-}

// exact unsigned division p/d for p<256, d in [1,16]: (p*magic)>>16
__constant__ unsigned c_magic[17] = {
    65536u, 65536u, 32768u, 21846u, 16384u, 13108u, 10923u, 9363u,
    8192u, 7282u, 6554u, 5958u, 5462u, 5042u, 4682u, 4370u, 4096u };

// ---------------------------------------------------------------------------
__device__ __forceinline__ bool gbounds(float cx, float cy, float cz, float r,
                                        int& x0, int& x1, int& y0, int& y1,
                                        int& z0, int& z1)
{
    const int bx = (int)floorf(cx);
    const int by = (int)floorf(cy);
    const int bz = (int)floorf(cz);
    x0 = max((int)floorf(cx - r), max(bx - RWIN, 0));
    x1 = min((int)ceilf (cx + r), min(bx + RWIN, GD - 1));
    y0 = max((int)floorf(cy - r), max(by - RWIN, 0));
    y1 = min((int)ceilf (cy + r), min(by + RWIN, GH - 1));
    z0 = max((int)floorf(cz - r), max(bz - RWIN, 0));
    z1 = min((int)ceilf (cz + r), min(bz + RWIN, GW - 1));
    return (x0 <= x1) && (y0 <= y1) && (z0 <= z1);
}

// ---------------------------------------------------------------------------
// Binning into per-(16^3-tile x 2-z-slice) buckets + param packing.
// pr.x = gid; pr.y = tile-local bounds lx0,lx1,ly0,ly1,lz0,lz1 (4b each).
// A pair is emitted once per z-slice it overlaps -> in splat, EVERY bucket
// entry engages its owning warp (no scans, no skips).
// ---------------------------------------------------------------------------
__global__ __launch_bounds__(64)
void scatter_kernel(const float* __restrict__ center,
                    const float* __restrict__ covinv,
                    const float* __restrict__ dens_r,
                    const float* __restrict__ dens_i,
                    const float* __restrict__ radius, int N)
{
    int g = blockIdx.x * blockDim.x + threadIdx.x;
    if (g >= N) return;

    const float cx = center[3*g+0], cy = center[3*g+1], cz = center[3*g+2];

    g_params[3*g+0] = make_float4(cx, cy, cz, covinv[9*g+0]);
    g_params[3*g+1] = make_float4(covinv[9*g+4], covinv[9*g+8],
                                  covinv[9*g+1] + covinv[9*g+3],
                                  covinv[9*g+2] + covinv[9*g+6]);
    g_params[3*g+2] = make_float4(covinv[9*g+5] + covinv[9*g+7],
                                  dens_r[g], dens_i[g], 0.0f);

    int x0, x1, y0, y1, z0, z1;
    if (!gbounds(cx, cy, cz, radius[g], x0, x1, y0, y1, z0, z1)) return;

    for (int tx = x0 >> 4; tx <= (x1 >> 4); ++tx) {
        const int xb = tx * TS;
        const unsigned lx0 = (unsigned)max(x0 - xb, 0);
        const unsigned lx1 = (unsigned)min(x1 - xb, TS - 1);
        for (int ty = y0 >> 4; ty <= (y1 >> 4); ++ty) {
            const int yb = ty * TS;
            const unsigned ly0 = (unsigned)max(y0 - yb, 0);
            const unsigned ly1 = (unsigned)min(y1 - yb, TS - 1);
            for (int tz = z0 >> 4; tz <= (z1 >> 4); ++tz) {
                const int zb = tz * TS;
                const unsigned lz0 = (unsigned)max(z0 - zb, 0);
                const unsigned lz1 = (unsigned)min(z1 - zb, TS - 1);
                const unsigned bb = lx0 | (lx1 << 4) | (ly0 << 8) |
                                    (ly1 << 12) | (lz0 << 16) | (lz1 << 20);
                const int tile = (tx * NT + ty) * NT + tz;
                const uint2 pr = make_uint2((unsigned)g, bb);
                const int s0 = (int)(lz0 >> 1), s1 = (int)(lz1 >> 1);
                for (int s = s0; s <= s1; ++s) {
                    const int bk = tile * 8 + s;
                    const int slot = atomicAdd(&g_cursors2[bk], 1);
                    if (slot < CAP2) g_pairs2[bk * CAP2 + slot] = pr;
                }
            }
        }
    }
}

// ---------------------------------------------------------------------------
// One 256-thread CTA per 16^3 tile. WARP w exclusively owns z-slice
// {2w, 2w+1} AND its own bucket b*8+w: every entry engages -> no scans,
// no staging, no __syncthreads in the main loop.
//  * compacted xy loop (p = lane .. nxy step 32; exact magic division):
//    ~100% lane efficiency
//  * edge-z validity folded into wr/wi via FSEL (warp-uniform)
//  * per cell: L0/L1 via 4 FMA, 2 FSEL + 2 ex2 (ftz(-1000)==+0 masks Md>9),
//    one float4 LDS/STS RMW covers both z
//  * pair + params read as warp-uniform __ldg broadcasts, MLP=4
//  * sAcc padded [8][257] -> conflict-free main loop AND transpose writeout
//  * coalesced float4 writeout; cursor self-reset for next graph replay
// ---------------------------------------------------------------------------
__global__ __launch_bounds__(256)
void splat_tiles_kernel(const float* __restrict__ half_shape,
                        float* __restrict__ out)
{
    const int b  = blockIdx.x;
    const int tz = b & 15, ty = (b >> 4) & 15, tx = b >> 8;
    const int xb = tx * TS, yb = ty * TS, zb = tz * TS;

    const int tid  = threadIdx.x;
    const int wid  = tid >> 5;
    const int lane = tid & 31;
    const int zlo  = 2 * wid;              // warp-owned z (tile-local)
    const int zhi  = zlo + 1;

    __shared__ float4 sAcc[8][257];        // padded: conflict-free transpose

    // zero own slice (warp-private; no pre-sync needed)
    #pragma unroll
    for (int j = 0; j < 8; ++j)
        sAcc[wid][j * 32 + lane] = make_float4(0.f, 0.f, 0.f, 0.f);

    const int bidx = b * 8 + wid;
    const int cnt  = min(g_cursors2[bidx], CAP2);   // warp-uniform broadcast
    if (lane == 0) g_cursors2[bidx] = 0;            // self-reset for replay
    const uint2* __restrict__ bucket = g_pairs2 + bidx * CAP2;

    const float ihx = 1.0f / half_shape[0];
    const float ihy = 1.0f / half_shape[1];
    const float e   = 1.0f / half_shape[2];

    const float h   = -0.72134752044448170f;   // -0.5 * log2(e)
    const float Lth = -6.49212768400033530f;   // 9*h  (Md<=9 <=> L>=Lth)
    const float he  = h * e;
    const float zgf = (float)(zb + zlo);        // this warp's global z

    for (int i = 0; i < cnt; ++i) {
        // MLP=4: issue all loads up-front (warp-uniform broadcasts)
        const uint2 pr = __ldg(bucket + i);
        const int g = (int)pr.x;
        const float4 p0 = __ldg(&g_params[3*g+0]);
        const float4 p1 = __ldg(&g_params[3*g+1]);
        const float4 p2 = __ldg(&g_params[3*g+2]);
        const unsigned bbp = pr.y;

        const int lx0 = bbp & 15,        lx1 = (bbp >> 4) & 15;
        const int ly0 = (bbp >> 8) & 15, ly1 = (bbp >> 12) & 15;
        const int lz0 = (bbp >> 16) & 15, lz1 = (bbp >> 20) & 15;
        const int nyp = ly1 - ly0 + 1;
        const int nxy = (lx1 - lx0 + 1) * nyp;
        const unsigned magic = c_magic[nyp];

        const float cx = p0.x, cy = p0.y, cz = p0.z, C00 = p0.w;
        const float C11 = p1.x, C22 = p1.y, S01 = p1.z, S02 = p1.w;
        const float S12 = p2.x;

        // edge-z validity folded into weights (warp-uniform FSELs)
        const bool v0 = (zlo >= lz0) & (zlo <= lz1);
        const bool v1 = (zhi >= lz0) & (zhi <= lz1);
        const float wr0 = v0 ? p2.y : 0.0f;
        const float wi0 = v0 ? p2.z : 0.0f;
        const float wr1 = v1 ? p2.y : 0.0f;
        const float wi1 = v1 ? p2.z : 0.0f;

        // pair+warp uniform z constants
        const float dz0 = (zgf - cz) * e;
        const float hdz = h * dz0;
        const float hCz = h * C22 * dz0 * dz0;
        const float hk1 = h * C22 * e * fmaf(2.0f, dz0, e);

        const float dxb = ((float)(xb + lx0) - cx) * ihx;
        const float dyb = ((float)(yb + ly0) - cy) * ihy;
        const int cellb = lx0 * 16 + ly0;

        for (int p = lane; p < nxy; p += 32) {
            const int ox = (int)(((unsigned)p * magic) >> 16);
            const int oy = p - ox * nyp;

            const float dx = fmaf((float)ox, ihx, dxb);
            const float dy = fmaf((float)oy, ihy, dyb);

            const float Bxy = fmaf(S02, dx, S12 * dy);
            const float Cxy = fmaf(fmaf(C00, dx, S01 * dy), dx,
                                   C11 * dy * dy);

            const float L0 = fmaf(hdz, Bxy, fmaf(h, Cxy, hCz));
            const float L1 = fmaf(he, Bxy, L0 + hk1);

            const float Ls0 = (L0 >= Lth) ? L0 : -1000.0f;
            const float Ls1 = (L1 >= Lth) ? L1 : -1000.0f;
            float w0, w1;
            asm("ex2.approx.ftz.f32 %0, %1;" : "=f"(w0) : "f"(Ls0));
            asm("ex2.approx.ftz.f32 %0, %1;" : "=f"(w1) : "f"(Ls1));

            const int cell = cellb + ox * 16 + oy;
            float4 v = sAcc[wid][cell];
            v.x = fmaf(w0, wr0, v.x);
            v.y = fmaf(w0, wi0, v.y);
            v.z = fmaf(w1, wr1, v.z);
            v.w = fmaf(w1, wi1, v.w);
            sAcc[wid][cell] = v;
        }
    }

    __syncthreads();

    // writeout: q=(cell c, z-quad k): lanes 0-3 share c (64B contiguous z),
    // quad z {4k..4k+3} = slices 2k (z 4k,4k+1) and 2k+1 (z 4k+2,4k+3).
    #pragma unroll
    for (int j = 0; j < 4; ++j) {
        const int q = tid + 256 * j;        // 0..1023
        const int c = q >> 2;               // cell 0..255
        const int k = q & 3;                // z quad
        const float4 a  = sAcc[2*k + 0][c];
        const float4 bq = sAcc[2*k + 1][c];
        const int gx = xb + (c >> 4);
        const int gy = yb + (c & 15);
        const int idx = (gx * GH + gy) * GW + zb + 4 * k;
        *(float4*)(out + idx)         = make_float4(a.x, a.z, bq.x, bq.z);
        *(float4*)(out + idx + DHW_I) = make_float4(a.y, a.w, bq.y, bq.w);
    }
}

// ---------------------------------------------------------------------------
extern "C" void kernel_launch(void* const* d_in, const int* in_sizes, int n_in,
                              void* d_out, int out_size) {
    const float* center     = (const float*)d_in[0];
    const float* covinv     = (const float*)d_in[1];
    const float* dens_r     = (const float*)d_in[2];
    const float* dens_i     = (const float*)d_in[3];
    const float* radius     = (const float*)d_in[4];
    const float* half_shape = (const float*)d_in[5];

    float* out = (float*)d_out;
    const int N = in_sizes[2];

    scatter_kernel<<<(N + 63) / 64, 64>>>(center, covinv, dens_r, dens_i,
                                          radius, N);
    splat_tiles_kernel<<<NTILES, 256>>>(half_shape, out);
}

// round 15
// speedup vs baseline: 1.3333x; 1.3333x over previous
#include <cuda_runtime.h>
#include <cstdint>

#define GD 256
#define GH 256
#define GW 256
#define NT 16
#define TS 16
#define RWIN 6
#define DHW_I 16777216
#define NTILES 4096
#define CAP 512
#define MAXN 32768
#define CHUNK 64

// zero-initialized at module load; splat resets cursors each replay
__device__ int    g_cursors[NTILES];
__device__ uint2  g_pairs  [NTILES * CAP];
__device__ float4 g_params [MAXN * 3];  // {cx,cy,cz,C00},{C11,C22,S01,S02},{S12,wr,wi,-}

// exact unsigned division p/d for p<256, d in [1,16]: (p*magic)>>16
__constant__ unsigned c_magic[17] = {
    65536u, 65536u, 32768u, 21846u, 16384u, 13108u, 10923u, 9363u,
    8192u, 7282u, 6554u, 5958u, 5462u, 5042u, 4682u, 4370u, 4096u };

// ---------------------------------------------------------------------------
// Binning into 16^3-tile buckets + param packing + ELLIPSOID-TIGHTENED bbox:
// {Md<=9} lies exactly inside |v_i - c_i| <= hs_i * sqrt(9 * (Cinv)_ii)
// (cofactor diagonal / det). Intersecting with the radius bbox is exactly
// conservative: excluded voxels have Md>9, whose weight the splat masks to 0.
// ---------------------------------------------------------------------------
__global__ __launch_bounds__(64)
void scatter_kernel(const float* __restrict__ center,
                    const float* __restrict__ covinv,
                    const float* __restrict__ dens_r,
                    const float* __restrict__ dens_i,
                    const float* __restrict__ radius,
                    const float* __restrict__ half_shape, int N)
{
    int g = blockIdx.x * blockDim.x + threadIdx.x;
    if (g >= N) return;

    const float cx = center[3*g+0], cy = center[3*g+1], cz = center[3*g+2];
    const float C00 = covinv[9*g+0], C01 = covinv[9*g+1], C02 = covinv[9*g+2];
    const float C10 = covinv[9*g+3], C11 = covinv[9*g+4], C12 = covinv[9*g+5];
    const float C20 = covinv[9*g+6], C21 = covinv[9*g+7], C22 = covinv[9*g+8];

    g_params[3*g+0] = make_float4(cx, cy, cz, C00);
    g_params[3*g+1] = make_float4(C11, C22, C01 + C10, C02 + C20);
    g_params[3*g+2] = make_float4(C12 + C21, dens_r[g], dens_i[g], 0.0f);

    // exact ellipsoid axis extents (symmetric SPD: use symmetrized terms)
    const float s01 = 0.5f * (C01 + C10);
    const float s02 = 0.5f * (C02 + C20);
    const float s12 = 0.5f * (C12 + C21);
    const float co00 = C11 * C22 - s12 * s12;       // cofactors (diag)
    const float co11 = C00 * C22 - s02 * s02;
    const float co22 = C00 * C11 - s01 * s01;
    const float det  = C00 * co00 - s01 * (s01 * C22 - s12 * s02)
                       + s02 * (s01 * s12 - C11 * s02);
    const float idet9 = 9.0001f / det;              // tiny safety margin
    const float extx = half_shape[0] * sqrtf(co00 * idet9);
    const float exty = half_shape[1] * sqrtf(co11 * idet9);
    const float extz = half_shape[2] * sqrtf(co22 * idet9);

    const float r  = radius[g];
    const int bx = (int)floorf(cx), by = (int)floorf(cy), bz = (int)floorf(cz);

    int x0 = max(max((int)floorf(cx - r), (int)ceilf(cx - extx)), max(bx - RWIN, 0));
    int x1 = min(min((int)ceilf (cx + r), (int)floorf(cx + extx)), min(bx + RWIN, GD - 1));
    int y0 = max(max((int)floorf(cy - r), (int)ceilf(cy - exty)), max(by - RWIN, 0));
    int y1 = min(min((int)ceilf (cy + r), (int)floorf(cy + exty)), min(by + RWIN, GH - 1));
    int z0 = max(max((int)floorf(cz - r), (int)ceilf(cz - extz)), max(bz - RWIN, 0));
    int z1 = min(min((int)ceilf (cz + r), (int)floorf(cz + extz)), min(bz + RWIN, GW - 1));
    if (x0 > x1 || y0 > y1 || z0 > z1) return;

    for (int tx = x0 >> 4; tx <= (x1 >> 4); ++tx) {
        const int xb = tx * TS;
        const unsigned lx0 = (unsigned)max(x0 - xb, 0);
        const unsigned lx1 = (unsigned)min(x1 - xb, TS - 1);
        for (int ty = y0 >> 4; ty <= (y1 >> 4); ++ty) {
            const int yb = ty * TS;
            const unsigned ly0 = (unsigned)max(y0 - yb, 0);
            const unsigned ly1 = (unsigned)min(y1 - yb, TS - 1);
            for (int tz = z0 >> 4; tz <= (z1 >> 4); ++tz) {
                const int zb = tz * TS;
                const unsigned lz0 = (unsigned)max(z0 - zb, 0);
                const unsigned lz1 = (unsigned)min(z1 - zb, TS - 1);
                const unsigned bb = lx0 | (lx1 << 4) | (ly0 << 8) |
                                    (ly1 << 12) | (lz0 << 16) | (lz1 << 20);
                const int tile = (tx * NT + ty) * NT + tz;
                const int slot = atomicAdd(&g_cursors[tile], 1);
                if (slot < CAP)
                    g_pairs[tile * CAP + slot] = make_uint2((unsigned)g, bb);
            }
        }
    }
}

// ---------------------------------------------------------------------------
// One 256-thread CTA per 16^3 tile. WARP w exclusively owns z-slice {2w,2w+1}
// (sAcc[w][cell] float4 = r/i for both z -> warp-private, no races).
//  * ballot-built engagement masks at staging: each warp iterates ONLY its
//    engaged pairs via ffs-bit loop (no scan/branch over the whole chunk)
//  * compacted xy loop (p = lane .. nxy step 32; exact magic division):
//    ~100% lane efficiency, no xy masks
//  * edge-z validity folded into wr/wi via FSEL (warp-uniform)
//  * per cell: L0/L1 via 4 FMA, 2 FSEL + 2 ex2 (ftz(-1000)==+0 masks Md>9),
//    one float4 LDS/STS RMW covers both z
//  * sAcc padded [8][257] -> conflict-free main loop AND transpose writeout
//  * coalesced float4 writeout; cursor self-reset for next graph replay
// ---------------------------------------------------------------------------
__global__ __launch_bounds__(256)
void splat_tiles_kernel(const float* __restrict__ half_shape,
                        float* __restrict__ out)
{
    const int b  = blockIdx.x;
    const int tz = b & 15, ty = (b >> 4) & 15, tx = b >> 8;
    const int xb = tx * TS, yb = ty * TS, zb = tz * TS;

    const int tid  = threadIdx.x;
    const int wid  = tid >> 5;
    const int lane = tid & 31;
    const int zlo  = 2 * wid;              // warp-owned z (tile-local)
    const int zhi  = zlo + 1;

    __shared__ float4   sAcc[8][257];      // padded: conflict-free transpose
    __shared__ float4   sp4[CHUNK * 3];
    __shared__ unsigned sbnd[CHUNK];
    __shared__ unsigned smask[8][2];       // [slice][chunk word]
    __shared__ int      scnt;

    // zero own slice (warp-private; no pre-sync needed)
    #pragma unroll
    for (int j = 0; j < 8; ++j)
        sAcc[wid][j * 32 + lane] = make_float4(0.f, 0.f, 0.f, 0.f);

    if (tid == 0) {
        scnt = min(g_cursors[b], CAP);
        g_cursors[b] = 0;                  // self-reset for next replay
    }
    __syncthreads();

    const float ihx = 1.0f / half_shape[0];
    const float ihy = 1.0f / half_shape[1];
    const float e   = 1.0f / half_shape[2];

    const int cnt = scnt;
    const uint2* __restrict__ bucket = g_pairs + b * CAP;

    const float h   = -0.72134752044448170f;   // -0.5 * log2(e)
    const float Lth = -6.49212768400033530f;   // 9*h  (Md<=9 <=> L>=Lth)
    const float he  = h * e;
    const float zgf = (float)(zb + zlo);        // this warp's global z

    for (int base = 0; base < cnt; base += CHUNK) {
        const int n = min(cnt - base, CHUNK);
        __syncthreads();
        unsigned eng = 0;                  // slice-engagement bits of my pair
        if (tid < n) {
            const uint2 pr = bucket[base + tid];
            const int g = (int)pr.x;
            sp4[3*tid+0] = g_params[3*g+0];
            sp4[3*tid+1] = g_params[3*g+1];
            sp4[3*tid+2] = g_params[3*g+2];
            sbnd[tid] = pr.y;
            const int s0 = (int)((pr.y >> 17) & 7);   // lz0 >> 1
            const int s1 = (int)((pr.y >> 21) & 7);   // lz1 >> 1
            eng = ((2u << (s1 - s0)) - 1u) << s0;
        }
        if (wid < 2) {                     // staging warps build ballots
            #pragma unroll
            for (int s = 0; s < 8; ++s) {
                const unsigned bal = __ballot_sync(0xFFFFFFFFu,
                                                   (eng >> s) & 1u);
                if (lane == 0) smask[s][wid] = bal;
            }
        }
        __syncthreads();

        #pragma unroll
        for (int jw = 0; jw < 2; ++jw) {
            unsigned m = smask[wid][jw];
            const int ib = jw << 5;
            while (m) {
                const int i = ib + __ffs(m) - 1;
                m &= m - 1;

                const unsigned bbp = sbnd[i];
                const int lx0 = bbp & 15,         lx1 = (bbp >> 4) & 15;
                const int ly0 = (bbp >> 8) & 15,  ly1 = (bbp >> 12) & 15;
                const int lz0 = (bbp >> 16) & 15, lz1 = (bbp >> 20) & 15;
                const int nyp = ly1 - ly0 + 1;
                const int nxy = (lx1 - lx0 + 1) * nyp;
                const unsigned magic = c_magic[nyp];

                const float4 p0 = sp4[3*i+0];
                const float4 p1 = sp4[3*i+1];
                const float4 p2 = sp4[3*i+2];
                const float cx = p0.x, cy = p0.y, cz = p0.z, C00 = p0.w;
                const float C11 = p1.x, C22 = p1.y, S01 = p1.z, S02 = p1.w;
                const float S12 = p2.x;

                // edge-z validity folded into weights (warp-uniform FSELs)
                const bool v0 = (zlo >= lz0) & (zlo <= lz1);
                const bool v1 = (zhi >= lz0) & (zhi <= lz1);
                const float wr0 = v0 ? p2.y : 0.0f;
                const float wi0 = v0 ? p2.z : 0.0f;
                const float wr1 = v1 ? p2.y : 0.0f;
                const float wi1 = v1 ? p2.z : 0.0f;

                // pair+warp uniform z constants
                const float dz0 = (zgf - cz) * e;
                const float hdz = h * dz0;
                const float hCz = h * C22 * dz0 * dz0;
                const float hk1 = h * C22 * e * fmaf(2.0f, dz0, e);

                const float dxb = ((float)(xb + lx0) - cx) * ihx;
                const float dyb = ((float)(yb + ly0) - cy) * ihy;
                const int cellb = lx0 * 16 + ly0;

                for (int p = lane; p < nxy; p += 32) {
                    const int ox = (int)(((unsigned)p * magic) >> 16);
                    const int oy = p - ox * nyp;

                    const float dx = fmaf((float)ox, ihx, dxb);
                    const float dy = fmaf((float)oy, ihy, dyb);

                    const float Bxy = fmaf(S02, dx, S12 * dy);
                    const float Cxy = fmaf(fmaf(C00, dx, S01 * dy), dx,
                                           C11 * dy * dy);

                    const float L0 = fmaf(hdz, Bxy, fmaf(h, Cxy, hCz));
                    const float L1 = fmaf(he, Bxy, L0 + hk1);

                    const float Ls0 = (L0 >= Lth) ? L0 : -1000.0f;
                    const float Ls1 = (L1 >= Lth) ? L1 : -1000.0f;
                    float w0, w1;
                    asm("ex2.approx.ftz.f32 %0, %1;" : "=f"(w0) : "f"(Ls0));
                    asm("ex2.approx.ftz.f32 %0, %1;" : "=f"(w1) : "f"(Ls1));

                    const int cell = cellb + ox * 16 + oy;
                    float4 v = sAcc[wid][cell];
                    v.x = fmaf(w0, wr0, v.x);
                    v.y = fmaf(w0, wi0, v.y);
                    v.z = fmaf(w1, wr1, v.z);
                    v.w = fmaf(w1, wi1, v.w);
                    sAcc[wid][cell] = v;
                }
            }
        }
    }

    __syncthreads();

    // writeout: q=(cell c, z-quad k): lanes 0-3 share c (64B contiguous z),
    // quad z {4k..4k+3} = slices 2k (z 4k,4k+1) and 2k+1 (z 4k+2,4k+3).
    #pragma unroll
    for (int j = 0; j < 4; ++j) {
        const int q = tid + 256 * j;        // 0..1023
        const int c = q >> 2;               // cell 0..255
        const int k = q & 3;                // z quad
        const float4 a  = sAcc[2*k + 0][c];
        const float4 bq = sAcc[2*k + 1][c];
        const int gx = xb + (c >> 4);
        const int gy = yb + (c & 15);
        const int idx = (gx * GH + gy) * GW + zb + 4 * k;
        *(float4*)(out + idx)         = make_float4(a.x, a.z, bq.x, bq.z);
        *(float4*)(out + idx + DHW_I) = make_float4(a.y, a.w, bq.y, bq.w);
    }
}

// ---------------------------------------------------------------------------
extern "C" void kernel_launch(void* const* d_in, const int* in_sizes, int n_in,
                              void* d_out, int out_size) {
    const float* center     = (const float*)d_in[0];
    const float* covinv     = (const float*)d_in[1];
    const float* dens_r     = (const float*)d_in[2];
    const float* dens_i     = (const float*)d_in[3];
    const float* radius     = (const float*)d_in[4];
    const float* half_shape = (const float*)d_in[5];

    float* out = (float*)d_out;
    const int N = in_sizes[2];

    scatter_kernel<<<(N + 63) / 64, 64>>>(center, covinv, dens_r, dens_i,
                                          radius, half_shape, N);
    splat_tiles_kernel<<<NTILES, 256>>>(half_shape, out);
}

// round 16
// speedup vs baseline: 1.3813x; 1.0359x over previous
#include <cuda_runtime.h>
#include <cstdint>

#define GD 256
#define GH 256
#define GW 256
#define NT 16
#define TS 16
#define RWIN 6
#define DHW_I 16777216
#define NTILES 4096
#define CAP 512
#define MAXN 32768
#define CHUNK 64

// zero-initialized at module load; splat resets cursors each replay
__device__ int    g_cursors[NTILES];
__device__ uint2  g_pairs  [NTILES * CAP];
__device__ float4 g_params [MAXN * 3];  // {cx,cy,cz,ha},{hb,hc,hd,hf},{hg,wr,wi,-}

// exact unsigned division p/d for p<256, d in [1,16]: (p*magic)>>16
__constant__ unsigned c_magic[17] = {
    65536u, 65536u, 32768u, 21846u, 16384u, 13108u, 10923u, 9363u,
    8192u, 7282u, 6554u, 5958u, 5462u, 5042u, 4682u, 4370u, 4096u };

// ---------------------------------------------------------------------------
// Binning into 16^3-tile buckets + PRE-SCALED param packing + ellipsoid-
// tightened bbox. Coefficients are pre-multiplied by h = -0.5*log2(e) and the
// normalization (1/half_shape) products, so the splat computes
// L = log2(w) directly from voxel-unit offsets with no extra constants.
// ---------------------------------------------------------------------------
__global__ __launch_bounds__(64)
void scatter_kernel(const float* __restrict__ center,
                    const float* __restrict__ covinv,
                    const float* __restrict__ dens_r,
                    const float* __restrict__ dens_i,
                    const float* __restrict__ radius,
                    const float* __restrict__ half_shape, int N)
{
    int g = blockIdx.x * blockDim.x + threadIdx.x;
    if (g >= N) return;

    const float cx = center[3*g+0], cy = center[3*g+1], cz = center[3*g+2];
    const float C00 = covinv[9*g+0], C01 = covinv[9*g+1], C02 = covinv[9*g+2];
    const float C10 = covinv[9*g+3], C11 = covinv[9*g+4], C12 = covinv[9*g+5];
    const float C20 = covinv[9*g+6], C21 = covinv[9*g+7], C22 = covinv[9*g+8];

    const float ihx = 1.0f / half_shape[0];
    const float ihy = 1.0f / half_shape[1];
    const float ihz = 1.0f / half_shape[2];
    const float h   = -0.72134752044448170f;   // -0.5 * log2(e)

    g_params[3*g+0] = make_float4(cx, cy, cz, h * C00 * ihx * ihx);
    g_params[3*g+1] = make_float4(h * (C01 + C10) * ihx * ihy,
                                  h * C11 * ihy * ihy,
                                  h * (C02 + C20) * ihx * ihz,
                                  h * (C12 + C21) * ihy * ihz);
    g_params[3*g+2] = make_float4(h * C22 * ihz * ihz,
                                  dens_r[g], dens_i[g], 0.0f);

    // exact ellipsoid axis extents (cofactor diagonal / det)
    const float s01 = 0.5f * (C01 + C10);
    const float s02 = 0.5f * (C02 + C20);
    const float s12 = 0.5f * (C12 + C21);
    const float co00 = C11 * C22 - s12 * s12;
    const float co11 = C00 * C22 - s02 * s02;
    const float co22 = C00 * C11 - s01 * s01;
    const float det  = C00 * co00 - s01 * (s01 * C22 - s12 * s02)
                       + s02 * (s01 * s12 - C11 * s02);
    const float idet9 = 9.0001f / det;
    const float extx = half_shape[0] * sqrtf(co00 * idet9);
    const float exty = half_shape[1] * sqrtf(co11 * idet9);
    const float extz = half_shape[2] * sqrtf(co22 * idet9);

    const float r  = radius[g];
    const int bx = (int)floorf(cx), by = (int)floorf(cy), bz = (int)floorf(cz);

    int x0 = max(max((int)floorf(cx - r), (int)ceilf(cx - extx)), max(bx - RWIN, 0));
    int x1 = min(min((int)ceilf (cx + r), (int)floorf(cx + extx)), min(bx + RWIN, GD - 1));
    int y0 = max(max((int)floorf(cy - r), (int)ceilf(cy - exty)), max(by - RWIN, 0));
    int y1 = min(min((int)ceilf (cy + r), (int)floorf(cy + exty)), min(by + RWIN, GH - 1));
    int z0 = max(max((int)floorf(cz - r), (int)ceilf(cz - extz)), max(bz - RWIN, 0));
    int z1 = min(min((int)ceilf (cz + r), (int)floorf(cz + extz)), min(bz + RWIN, GW - 1));
    if (x0 > x1 || y0 > y1 || z0 > z1) return;

    for (int tx = x0 >> 4; tx <= (x1 >> 4); ++tx) {
        const int xb = tx * TS;
        const unsigned lx0 = (unsigned)max(x0 - xb, 0);
        const unsigned lx1 = (unsigned)min(x1 - xb, TS - 1);
        for (int ty = y0 >> 4; ty <= (y1 >> 4); ++ty) {
            const int yb = ty * TS;
            const unsigned ly0 = (unsigned)max(y0 - yb, 0);
            const unsigned ly1 = (unsigned)min(y1 - yb, TS - 1);
            for (int tz = z0 >> 4; tz <= (z1 >> 4); ++tz) {
                const int zb = tz * TS;
                const unsigned lz0 = (unsigned)max(z0 - zb, 0);
                const unsigned lz1 = (unsigned)min(z1 - zb, TS - 1);
                const unsigned bb = lx0 | (lx1 << 4) | (ly0 << 8) |
                                    (ly1 << 12) | (lz0 << 16) | (lz1 << 20);
                const int tile = (tx * NT + ty) * NT + tz;
                const int slot = atomicAdd(&g_cursors[tile], 1);
                if (slot < CAP)
                    g_pairs[tile * CAP + slot] = make_uint2((unsigned)g, bb);
            }
        }
    }
}

// ---------------------------------------------------------------------------
// One 256-thread CTA per 16^3 tile. WARP w exclusively owns z-slice {2w,2w+1}
// (sAcc[w][cell] float4 = r/i for both z -> warp-private, no races).
//  * __launch_bounds__(256, 6): force 6 CTAs/SM (48 warps, was 5/40)
//  * pre-scaled coefficients: no half_shape/log2 constants live in the loop
//  * ballot-built engagement masks; ffs-bit loop over engaged pairs only
//  * compacted xy loop (p = lane .. nxy step 32; exact magic division)
//  * L(z) in log2 domain: L0 = hB*zr + hQ + k0; L1 = L0 + hB + kd (voxel units)
//  * ex2.approx.ftz(-1000) == +0.0f masks Md>9 / invalid z
//  * sAcc padded [8][257] -> conflict-free main loop AND transpose writeout
// ---------------------------------------------------------------------------
__global__ __launch_bounds__(256, 6)
void splat_tiles_kernel(float* __restrict__ out)
{
    const int b  = blockIdx.x;
    const int tz = b & 15, ty = (b >> 4) & 15, tx = b >> 8;
    const int xb = tx * TS, yb = ty * TS, zb = tz * TS;

    const int tid  = threadIdx.x;
    const int wid  = tid >> 5;
    const int lane = tid & 31;
    const int zlo  = 2 * wid;              // warp-owned z (tile-local)
    const int zhi  = zlo + 1;

    __shared__ float4   sAcc[8][257];      // padded: conflict-free transpose
    __shared__ float4   sp4[CHUNK * 3];
    __shared__ unsigned sbnd[CHUNK];
    __shared__ unsigned smask[8][2];       // [slice][chunk word]
    __shared__ int      scnt;

    #pragma unroll
    for (int j = 0; j < 8; ++j)
        sAcc[wid][j * 32 + lane] = make_float4(0.f, 0.f, 0.f, 0.f);

    if (tid == 0) {
        scnt = min(g_cursors[b], CAP);
        g_cursors[b] = 0;                  // self-reset for next replay
    }
    __syncthreads();

    const int cnt = scnt;
    const uint2* __restrict__ bucket = g_pairs + b * CAP;

    const float Lth = -6.49212768400033530f;   // 9*h  (Md<=9 <=> L>=Lth)
    const float zgf = (float)(zb + zlo);       // this warp's global z (voxels)

    for (int base = 0; base < cnt; base += CHUNK) {
        const int n = min(cnt - base, CHUNK);
        __syncthreads();
        unsigned eng = 0;
        if (tid < n) {
            const uint2 pr = bucket[base + tid];
            const int g = (int)pr.x;
            sp4[3*tid+0] = g_params[3*g+0];
            sp4[3*tid+1] = g_params[3*g+1];
            sp4[3*tid+2] = g_params[3*g+2];
            sbnd[tid] = pr.y;
            const int s0 = (int)((pr.y >> 17) & 7);   // lz0 >> 1
            const int s1 = (int)((pr.y >> 21) & 7);   // lz1 >> 1
            eng = ((2u << (s1 - s0)) - 1u) << s0;
        }
        if (wid < 2) {
            #pragma unroll
            for (int s = 0; s < 8; ++s) {
                const unsigned bal = __ballot_sync(0xFFFFFFFFu,
                                                   (eng >> s) & 1u);
                if (lane == 0) smask[s][wid] = bal;
            }
        }
        __syncthreads();

        #pragma unroll
        for (int jw = 0; jw < 2; ++jw) {
            unsigned m = smask[wid][jw];
            const int ib = jw << 5;
            while (m) {
                const int i = ib + __ffs(m) - 1;
                m &= m - 1;

                const unsigned bbp = sbnd[i];
                const int lx0 = bbp & 15,         lx1 = (bbp >> 4) & 15;
                const int ly0 = (bbp >> 8) & 15,  ly1 = (bbp >> 12) & 15;
                const int lz0 = (bbp >> 16) & 15, lz1 = (bbp >> 20) & 15;
                const int nyp = ly1 - ly0 + 1;
                const int nxy = (lx1 - lx0 + 1) * nyp;
                const unsigned magic = c_magic[nyp];

                const float4 p0 = sp4[3*i+0];
                const float4 p1 = sp4[3*i+1];
                const float4 p2 = sp4[3*i+2];
                const float cx = p0.x, cy = p0.y, cz = p0.z, ha = p0.w;
                const float hb = p1.x, hc = p1.y, hd = p1.z, hf = p1.w;
                const float hg = p2.x;

                // edge-z validity folded into weights (warp-uniform FSELs)
                const bool v0 = (zlo >= lz0) & (zlo <= lz1);
                const bool v1 = (zhi >= lz0) & (zhi <= lz1);
                const float wr0 = v0 ? p2.y : 0.0f;
                const float wi0 = v0 ? p2.z : 0.0f;
                const float wr1 = v1 ? p2.y : 0.0f;
                const float wi1 = v1 ? p2.z : 0.0f;

                // pair+warp uniform z constants (voxel units)
                const float zr = zgf - cz;
                const float k0 = hg * zr * zr;
                const float kd = hg * fmaf(2.0f, zr, 1.0f);

                const float u0f = (float)(xb + lx0) - cx;
                const float v0f = (float)(yb + ly0) - cy;
                const int cellb = lx0 * 16 + ly0;

                for (int p = lane; p < nxy; p += 32) {
                    const int ox = (int)(((unsigned)p * magic) >> 16);
                    const int oy = p - ox * nyp;

                    const float u = u0f + (float)ox;
                    const float v = v0f + (float)oy;

                    const float hB = fmaf(hd, u, hf * v);
                    const float hQ = fmaf(fmaf(ha, u, hb * v), u,
                                          (hc * v) * v);

                    const float L0 = fmaf(hB, zr, hQ + k0);
                    const float L1 = L0 + hB + kd;

                    const float Ls0 = (L0 >= Lth) ? L0 : -1000.0f;
                    const float Ls1 = (L1 >= Lth) ? L1 : -1000.0f;
                    float w0, w1;
                    asm("ex2.approx.ftz.f32 %0, %1;" : "=f"(w0) : "f"(Ls0));
                    asm("ex2.approx.ftz.f32 %0, %1;" : "=f"(w1) : "f"(Ls1));

                    const int cell = cellb + ox * 16 + oy;
                    float4 acc = sAcc[wid][cell];
                    acc.x = fmaf(w0, wr0, acc.x);
                    acc.y = fmaf(w0, wi0, acc.y);
                    acc.z = fmaf(w1, wr1, acc.z);
                    acc.w = fmaf(w1, wi1, acc.w);
                    sAcc[wid][cell] = acc;
                }
            }
        }
    }

    __syncthreads();

    // writeout: q=(cell c, z-quad k): lanes 0-3 share c (64B contiguous z),
    // quad z {4k..4k+3} = slices 2k (z 4k,4k+1) and 2k+1 (z 4k+2,4k+3).
    #pragma unroll
    for (int j = 0; j < 4; ++j) {
        const int q = tid + 256 * j;        // 0..1023
        const int c = q >> 2;               // cell 0..255
        const int k = q & 3;                // z quad
        const float4 a  = sAcc[2*k + 0][c];
        const float4 bq = sAcc[2*k + 1][c];
        const int gx = xb + (c >> 4);
        const int gy = yb + (c & 15);
        const int idx = (gx * GH + gy) * GW + zb + 4 * k;
        *(float4*)(out + idx)         = make_float4(a.x, a.z, bq.x, bq.z);
        *(float4*)(out + idx + DHW_I) = make_float4(a.y, a.w, bq.y, bq.w);
    }
}

// ---------------------------------------------------------------------------
extern "C" void kernel_launch(void* const* d_in, const int* in_sizes, int n_in,
                              void* d_out, int out_size) {
    const float* center     = (const float*)d_in[0];
    const float* covinv     = (const float*)d_in[1];
    const float* dens_r     = (const float*)d_in[2];
    const float* dens_i     = (const float*)d_in[3];
    const float* radius     = (const float*)d_in[4];
    const float* half_shape = (const float*)d_in[5];

    float* out = (float*)d_out;
    const int N = in_sizes[2];

    scatter_kernel<<<(N + 63) / 64, 64>>>(center, covinv, dens_r, dens_i,
                                          radius, half_shape, N);
    splat_tiles_kernel<<<NTILES, 256>>>(out);
}

// round 17
// speedup vs baseline: 1.4551x; 1.0535x over previous
#include <cuda_runtime.h>
#include <cstdint>

#define GD 256
#define GH 256
#define GW 256
#define NT 16
#define TS 16
#define RWIN 6
#define DHW_I 16777216
#define NTILES 4096
#define CAP 512
#define MAXN 32768
#define CHUNK 64

// zero-initialized at module load; splat resets cursors each replay
__device__ int    g_cursors[NTILES];
__device__ uint2  g_pairs  [NTILES * CAP];
__device__ float4 g_params [MAXN * 3];  // {cx,cy,cz,ha},{hb,hc,hd,hf},{hg,wr,wi,-}

// exact unsigned division p/d for p<256, d in [1,16]: (p*magic)>>16
__constant__ unsigned c_magic[17] = {
    65536u, 65536u, 32768u, 21846u, 16384u, 13108u, 10923u, 9363u,
    8192u, 7282u, 6554u, 5958u, 5462u, 5042u, 4682u, 4370u, 4096u };

// ---------------------------------------------------------------------------
// Binning into 16^3-tile buckets + PRE-SCALED param packing + ellipsoid-
// tightened bbox (cofactor diagonal / det). Coefficients pre-multiplied by
// h = -0.5*log2(e) and 1/half_shape products: splat computes L = log2(w)
// directly from voxel-unit offsets.
// ---------------------------------------------------------------------------
__global__ __launch_bounds__(64)
void scatter_kernel(const float* __restrict__ center,
                    const float* __restrict__ covinv,
                    const float* __restrict__ dens_r,
                    const float* __restrict__ dens_i,
                    const float* __restrict__ radius,
                    const float* __restrict__ half_shape, int N)
{
    int g = blockIdx.x * blockDim.x + threadIdx.x;
    if (g >= N) return;

    const float cx = center[3*g+0], cy = center[3*g+1], cz = center[3*g+2];
    const float C00 = covinv[9*g+0], C01 = covinv[9*g+1], C02 = covinv[9*g+2];
    const float C10 = covinv[9*g+3], C11 = covinv[9*g+4], C12 = covinv[9*g+5];
    const float C20 = covinv[9*g+6], C21 = covinv[9*g+7], C22 = covinv[9*g+8];

    const float ihx = 1.0f / half_shape[0];
    const float ihy = 1.0f / half_shape[1];
    const float ihz = 1.0f / half_shape[2];
    const float h   = -0.72134752044448170f;   // -0.5 * log2(e)

    g_params[3*g+0] = make_float4(cx, cy, cz, h * C00 * ihx * ihx);
    g_params[3*g+1] = make_float4(h * (C01 + C10) * ihx * ihy,
                                  h * C11 * ihy * ihy,
                                  h * (C02 + C20) * ihx * ihz,
                                  h * (C12 + C21) * ihy * ihz);
    g_params[3*g+2] = make_float4(h * C22 * ihz * ihz,
                                  dens_r[g], dens_i[g], 0.0f);

    // exact ellipsoid axis extents (cofactor diagonal / det)
    const float s01 = 0.5f * (C01 + C10);
    const float s02 = 0.5f * (C02 + C20);
    const float s12 = 0.5f * (C12 + C21);
    const float co00 = C11 * C22 - s12 * s12;
    const float co11 = C00 * C22 - s02 * s02;
    const float co22 = C00 * C11 - s01 * s01;
    const float det  = C00 * co00 - s01 * (s01 * C22 - s12 * s02)
                       + s02 * (s01 * s12 - C11 * s02);
    const float idet9 = 9.0001f / det;
    const float extx = half_shape[0] * sqrtf(co00 * idet9);
    const float exty = half_shape[1] * sqrtf(co11 * idet9);
    const float extz = half_shape[2] * sqrtf(co22 * idet9);

    const float r  = radius[g];
    const int bx = (int)floorf(cx), by = (int)floorf(cy), bz = (int)floorf(cz);

    int x0 = max(max((int)floorf(cx - r), (int)ceilf(cx - extx)), max(bx - RWIN, 0));
    int x1 = min(min((int)ceilf (cx + r), (int)floorf(cx + extx)), min(bx + RWIN, GD - 1));
    int y0 = max(max((int)floorf(cy - r), (int)ceilf(cy - exty)), max(by - RWIN, 0));
    int y1 = min(min((int)ceilf (cy + r), (int)floorf(cy + exty)), min(by + RWIN, GH - 1));
    int z0 = max(max((int)floorf(cz - r), (int)ceilf(cz - extz)), max(bz - RWIN, 0));
    int z1 = min(min((int)ceilf (cz + r), (int)floorf(cz + extz)), min(bz + RWIN, GW - 1));
    if (x0 > x1 || y0 > y1 || z0 > z1) return;

    for (int tx = x0 >> 4; tx <= (x1 >> 4); ++tx) {
        const int xb = tx * TS;
        const unsigned lx0 = (unsigned)max(x0 - xb, 0);
        const unsigned lx1 = (unsigned)min(x1 - xb, TS - 1);
        for (int ty = y0 >> 4; ty <= (y1 >> 4); ++ty) {
            const int yb = ty * TS;
            const unsigned ly0 = (unsigned)max(y0 - yb, 0);
            const unsigned ly1 = (unsigned)min(y1 - yb, TS - 1);
            for (int tz = z0 >> 4; tz <= (z1 >> 4); ++tz) {
                const int zb = tz * TS;
                const unsigned lz0 = (unsigned)max(z0 - zb, 0);
                const unsigned lz1 = (unsigned)min(z1 - zb, TS - 1);
                const unsigned bb = lx0 | (lx1 << 4) | (ly0 << 8) |
                                    (ly1 << 12) | (lz0 << 16) | (lz1 << 20);
                const int tile = (tx * NT + ty) * NT + tz;
                const int slot = atomicAdd(&g_cursors[tile], 1);
                if (slot < CAP)
                    g_pairs[tile * CAP + slot] = make_uint2((unsigned)g, bb);
            }
        }
    }
}

// ---------------------------------------------------------------------------
// One 256-thread CTA per 16^3 tile. WARP w exclusively owns z-slice {2w,2w+1}
// (sAcc[w][cell] float4 = r/i for both z -> warp-private, no races).
//  * STAGE-TIME DECODE: each pair is decoded ONCE by the staging threads into
//    sGeo = {u0f, v0f, nxy|cellb<<16, zmask16|nyp<<16} + 2 coef float4s + wi;
//    engaged-warp visit setup = 4 LDS broadcasts + a few extracts
//  * POISON ANCHORS: z-validity folded into the quadratic's constant term
//    (k0 = valid ? hg*zr^2 : -1e4 -> L < Lth -> ex2 masks to exactly 0)
//  * ballot engagement masks; ffs loop over engaged pairs only
//  * compacted xy loop (p = lane .. nxy step 32; exact magic division)
//  * sAcc padded [8][257] -> conflict-free main loop AND transpose writeout
// ---------------------------------------------------------------------------
__global__ __launch_bounds__(256, 6)
void splat_tiles_kernel(float* __restrict__ out)
{
    const int b  = blockIdx.x;
    const int tz = b & 15, ty = (b >> 4) & 15, tx = b >> 8;
    const int xb = tx * TS, yb = ty * TS, zb = tz * TS;

    const int tid  = threadIdx.x;
    const int wid  = tid >> 5;
    const int lane = tid & 31;
    const int zlo  = 2 * wid;              // warp-owned z (tile-local)
    const int zhi  = zlo + 1;

    __shared__ float4   sAcc[8][257];      // padded: conflict-free transpose
    __shared__ float4   sGeo[CHUNK];       // {u0f, v0f, nxy|cellb, zmask|nyp}
    __shared__ float4   sCo1[CHUNK];       // {cz, ha, hb, hc}
    __shared__ float4   sCo2[CHUNK];       // {hd, hf, hg, wr}
    __shared__ float    sWi [CHUNK];
    __shared__ unsigned smask[8][2];       // [slice][chunk word]
    __shared__ int      scnt;

    #pragma unroll
    for (int j = 0; j < 8; ++j)
        sAcc[wid][j * 32 + lane] = make_float4(0.f, 0.f, 0.f, 0.f);

    if (tid == 0) {
        scnt = min(g_cursors[b], CAP);
        g_cursors[b] = 0;                  // self-reset for next replay
    }
    __syncthreads();

    const int cnt = scnt;
    const uint2* __restrict__ bucket = g_pairs + b * CAP;

    const float Lth = -6.49212768400033530f;   // 9*h  (Md<=9 <=> L>=Lth)
    const float zgf = (float)(zb + zlo);       // this warp's global z (voxels)

    for (int base = 0; base < cnt; base += CHUNK) {
        const int n = min(cnt - base, CHUNK);
        __syncthreads();
        unsigned eng = 0;
        if (tid < n) {
            const uint2 pr = bucket[base + tid];
            const int g = (int)pr.x;
            const unsigned bbp = pr.y;
            const float4 p0 = g_params[3*g+0];
            const float4 p1 = g_params[3*g+1];
            const float4 p2 = g_params[3*g+2];

            const int lx0 = bbp & 15,         lx1 = (bbp >> 4) & 15;
            const int ly0 = (bbp >> 8) & 15,  ly1 = (bbp >> 12) & 15;
            const int lz0 = (bbp >> 16) & 15, lz1 = (bbp >> 20) & 15;
            const int nyp = ly1 - ly0 + 1;
            const int nxy = (lx1 - lx0 + 1) * nyp;
            const int cellb = lx0 * 16 + ly0;
            const unsigned zmask = ((1u << (lz1 + 1)) - 1u) &
                                   ~((1u << lz0) - 1u);

            sGeo[tid] = make_float4(
                (float)(xb + lx0) - p0.x,
                (float)(yb + ly0) - p0.y,
                __int_as_float(nxy | (cellb << 16)),
                __int_as_float((int)(zmask | ((unsigned)nyp << 16))));
            sCo1[tid] = make_float4(p0.z, p0.w, p1.x, p1.y);
            sCo2[tid] = make_float4(p1.z, p1.w, p2.x, p2.y);
            sWi [tid] = p2.z;

            const int s0 = lz0 >> 1, s1 = lz1 >> 1;
            eng = ((2u << (s1 - s0)) - 1u) << s0;
        }
        if (wid < 2) {
            #pragma unroll
            for (int s = 0; s < 8; ++s) {
                const unsigned bal = __ballot_sync(0xFFFFFFFFu,
                                                   (eng >> s) & 1u);
                if (lane == 0) smask[s][wid] = bal;
            }
        }
        __syncthreads();

        #pragma unroll
        for (int jw = 0; jw < 2; ++jw) {
            unsigned m = smask[wid][jw];
            const int ib = jw << 5;
            while (m) {
                const int i = ib + __ffs(m) - 1;
                m &= m - 1;

                const float4 geo = sGeo[i];
                const float4 c1  = sCo1[i];
                const float4 c2  = sCo2[i];
                const float  wiv = sWi[i];

                const unsigned xc = __float_as_uint(geo.z);
                const unsigned zc = __float_as_uint(geo.w);
                const int nxy   = (int)(xc & 0xFFFFu);
                const int cellb = (int)(xc >> 16);
                const int nyp   = (int)(zc >> 16);
                const unsigned magic = c_magic[nyp];

                const float cz = c1.x, ha = c1.y, hb = c1.z, hc = c1.w;
                const float hd = c2.x, hf = c2.y, hg = c2.z, wrv = c2.w;

                // poison anchors: invalid z -> L << Lth -> ex2 masks to 0
                const float zr0 = zgf - cz;
                const float zr1 = zr0 + 1.0f;
                const float k0a = ((zc >> zlo) & 1u) ? hg * zr0 * zr0
                                                     : -1.0e4f;
                const float k0b = ((zc >> zhi) & 1u) ? hg * zr1 * zr1
                                                     : -1.0e4f;
                const float u0f = geo.x, v0f = geo.y;

                for (int p = lane; p < nxy; p += 32) {
                    const int ox = (int)(((unsigned)p * magic) >> 16);
                    const int oy = p - ox * nyp;

                    const float u = u0f + (float)ox;
                    const float v = v0f + (float)oy;

                    const float hB = fmaf(hd, u, hf * v);
                    const float hQ = fmaf(fmaf(ha, u, hb * v), u,
                                          (hc * v) * v);

                    const float L0 = fmaf(hB, zr0, hQ + k0a);
                    const float L1 = fmaf(hB, zr1, hQ + k0b);

                    const float Ls0 = (L0 >= Lth) ? L0 : -1000.0f;
                    const float Ls1 = (L1 >= Lth) ? L1 : -1000.0f;
                    float w0, w1;
                    asm("ex2.approx.ftz.f32 %0, %1;" : "=f"(w0) : "f"(Ls0));
                    asm("ex2.approx.ftz.f32 %0, %1;" : "=f"(w1) : "f"(Ls1));

                    const int cell = cellb + ox * 16 + oy;
                    float4 acc = sAcc[wid][cell];
                    acc.x = fmaf(w0, wrv, acc.x);
                    acc.y = fmaf(w0, wiv, acc.y);
                    acc.z = fmaf(w1, wrv, acc.z);
                    acc.w = fmaf(w1, wiv, acc.w);
                    sAcc[wid][cell] = acc;
                }
            }
        }
    }

    __syncthreads();

    // writeout: q=(cell c, z-quad k): lanes 0-3 share c (64B contiguous z),
    // quad z {4k..4k+3} = slices 2k (z 4k,4k+1) and 2k+1 (z 4k+2,4k+3).
    #pragma unroll
    for (int j = 0; j < 4; ++j) {
        const int q = tid + 256 * j;        // 0..1023
        const int c = q >> 2;               // cell 0..255
        const int k = q & 3;                // z quad
        const float4 a  = sAcc[2*k + 0][c];
        const float4 bq = sAcc[2*k + 1][c];
        const int gx = xb + (c >> 4);
        const int gy = yb + (c & 15);
        const int idx = (gx * GH + gy) * GW + zb + 4 * k;
        *(float4*)(out + idx)         = make_float4(a.x, a.z, bq.x, bq.z);
        *(float4*)(out + idx + DHW_I) = make_float4(a.y, a.w, bq.y, bq.w);
    }
}

// ---------------------------------------------------------------------------
extern "C" void kernel_launch(void* const* d_in, const int* in_sizes, int n_in,
                              void* d_out, int out_size) {
    const float* center     = (const float*)d_in[0];
    const float* covinv     = (const float*)d_in[1];
    const float* dens_r     = (const float*)d_in[2];
    const float* dens_i     = (const float*)d_in[3];
    const float* radius     = (const float*)d_in[4];
    const float* half_shape = (const float*)d_in[5];

    float* out = (float*)d_out;
    const int N = in_sizes[2];

    scatter_kernel<<<(N + 63) / 64, 64>>>(center, covinv, dens_r, dens_i,
                                          radius, half_shape, N);
    splat_tiles_kernel<<<NTILES, 256>>>(out);
}